// round 14
// baseline (speedup 1.0000x reference)
#include <cuda_runtime.h>
#include <cuda_fp16.h>
#include <cuda_bf16.h>
#include <stdint.h>

// Problem constants: N=100000, E=1600000, IN_DIM=128, H*D=128, head0 D=32
#define NNODES   100000
#define EMAX     1600000
#define FDIM     128
#define ALPHA    0.2f

// -------- scratch (allocation-free rule: __device__ globals) ---------------
__device__ __half  g_fth[NNODES * FDIM]; // fc output in fp16 (gather payload)
__device__ float   g_sl[NNODES];         // head-0 left scores (fp32)
__device__ float   g_sr[NNODES];         // head-0 right scores
__device__ float   g_vl[FDIM];           // fc_w[:,0:32] @ attn_l
__device__ float   g_vr[FDIM];           // fc_w[:,0:32] @ attn_r
__device__ int     g_deg[NNODES];
__device__ int     g_off[NNODES];
__device__ int     g_cur[NNODES];
__device__ float2  g_edge[EMAX];         // (src_as_float, w) per edge, CSR order
__device__ int     g_bsum[512];

// ---------------------------------------------------------------------------
// GEMM: bf16x3 (hi/lo split, 3 MMAs: hh + lh + hl) m16n8k16, scalar smem
// fragment loads (fastest measured config). Full B resident in smem.
// BM=128, 8 warps, warp tile 64x32. No epilogue fusion (scores decoupled).
// ---------------------------------------------------------------------------
#define ASW 20   // A chunk stride in words; frag loads bank (4g+t), conflict-free
#define BSW 68   // B stride in words; frag loads bank-clean
#define GEMM_SMEM_WORDS (2*128*BSW + 2*128*ASW)   // 22528 words = 90112 B

__device__ __forceinline__ void cvt_hilo(float x, float y, unsigned& h, unsigned& l) {
    __nv_bfloat162 hb = __floats2bfloat162_rn(x, y);
    float2 hf = __bfloat1622float2(hb);
    __nv_bfloat162 lb = __floats2bfloat162_rn(x - hf.x, y - hf.y);
    h = *reinterpret_cast<unsigned*>(&hb);
    l = *reinterpret_cast<unsigned*>(&lb);
}

__device__ __forceinline__ void mma_bf16(
    float& c0, float& c1, float& c2, float& c3,
    unsigned a0, unsigned a1, unsigned a2, unsigned a3,
    unsigned b0, unsigned b1)
{
    asm volatile(
        "mma.sync.aligned.m16n8k16.row.col.f32.bf16.bf16.f32 "
        "{%0,%1,%2,%3}, {%4,%5,%6,%7}, {%8,%9}, {%0,%1,%2,%3};"
        : "+f"(c0), "+f"(c1), "+f"(c2), "+f"(c3)
        : "r"(a0), "r"(a1), "r"(a2), "r"(a3), "r"(b0), "r"(b1));
}

__global__ void __launch_bounds__(256, 2) gemm_tc_kernel(
    const float* __restrict__ A, const float* __restrict__ B, int M)
{
    extern __shared__ unsigned sm[];
    unsigned* sBhi = sm;                       // 128*BSW
    unsigned* sBlo = sm + 128 * BSW;
    unsigned* sAhi = sm + 2 * 128 * BSW;       // 128*ASW
    unsigned* sAlo = sm + 2 * 128 * BSW + 128 * ASW;

    int tid  = threadIdx.x;
    int wid  = tid >> 5;
    int lane = tid & 31;
    int g    = lane >> 2;   // groupID 0..7
    int t    = lane & 3;    // thread-in-group 0..3
    int wM   = wid >> 2;    // 0..1  (64 rows each)
    int wN   = wid & 3;     // 0..3  (32 cols each)
    int rowBase = blockIdx.x * 128;

    // ---- load FULL B (128x128) once: hi/lo bf16, [n][k-pairs] ----
#pragma unroll
    for (int i = 0; i < 32; i++) {
        int w = i * 256 + tid;
        int n = w & 127;
        int kp = w >> 7;
        float f0 = B[(2 * kp) * 128 + n];
        float f1 = B[(2 * kp + 1) * 128 + n];
        unsigned h, l;
        cvt_hilo(f0, f1, h, l);
        sBhi[n * BSW + kp] = h;
        sBlo[n * BSW + kp] = l;
    }

    float acc[4][4][4];
#pragma unroll
    for (int i = 0; i < 4; i++)
#pragma unroll
        for (int j = 0; j < 4; j++)
#pragma unroll
            for (int k = 0; k < 4; k++) acc[i][j][k] = 0.0f;

    for (int kk = 0; kk < 128; kk += 32) {
        // ---- load A chunk 128x32 (1024 f4: 4 per thread), hi/lo bf16 ----
#pragma unroll
        for (int i = 0; i < 4; i++) {
            int idx = i * 256 + tid;
            int r  = idx >> 3;        // row 0..127
            int c4 = idx & 7;         // f4-col 0..7
            int gr = rowBase + r;
            float4 v = make_float4(0.f, 0.f, 0.f, 0.f);
            if (gr < M) v = *(const float4*)&A[gr * 128 + kk + c4 * 4];
            unsigned h0, l0, h1, l1;
            cvt_hilo(v.x, v.y, h0, l0);
            cvt_hilo(v.z, v.w, h1, l1);
            int o = r * ASW + c4 * 2;
            sAhi[o] = h0; sAhi[o + 1] = h1;
            sAlo[o] = l0; sAlo[o + 1] = l1;
        }
        __syncthreads();

#pragma unroll
        for (int ks = 0; ks < 2; ks++) {
            int kw  = ks * 8;          // word offset within A chunk
            int bkw = kk / 2 + ks * 8; // word offset within B rows

            unsigned bh[4][2], bl[4][2];
#pragma unroll
            for (int nf = 0; nf < 4; nf++) {
                int bn = wN * 32 + nf * 8 + g;
                bh[nf][0] = sBhi[bn * BSW + bkw + t];
                bh[nf][1] = sBhi[bn * BSW + bkw + t + 4];
                bl[nf][0] = sBlo[bn * BSW + bkw + t];
                bl[nf][1] = sBlo[bn * BSW + bkw + t + 4];
            }
#pragma unroll
            for (int mf = 0; mf < 4; mf++) {
                int ar = wM * 64 + mf * 16 + g;
                unsigned ah0 = sAhi[ar * ASW + kw + t];
                unsigned ah1 = sAhi[(ar + 8) * ASW + kw + t];
                unsigned ah2 = sAhi[ar * ASW + kw + t + 4];
                unsigned ah3 = sAhi[(ar + 8) * ASW + kw + t + 4];
                unsigned al0 = sAlo[ar * ASW + kw + t];
                unsigned al1 = sAlo[(ar + 8) * ASW + kw + t];
                unsigned al2 = sAlo[ar * ASW + kw + t + 4];
                unsigned al3 = sAlo[(ar + 8) * ASW + kw + t + 4];
#pragma unroll
                for (int nf = 0; nf < 4; nf++) {
                    mma_bf16(acc[mf][nf][0], acc[mf][nf][1], acc[mf][nf][2], acc[mf][nf][3],
                             ah0, ah1, ah2, ah3, bh[nf][0], bh[nf][1]);
                    mma_bf16(acc[mf][nf][0], acc[mf][nf][1], acc[mf][nf][2], acc[mf][nf][3],
                             al0, al1, al2, al3, bh[nf][0], bh[nf][1]);
                    mma_bf16(acc[mf][nf][0], acc[mf][nf][1], acc[mf][nf][2], acc[mf][nf][3],
                             ah0, ah1, ah2, ah3, bl[nf][0], bl[nf][1]);
                }
            }
        }
        __syncthreads();
    }

    // ---- epilogue: fp16 store only ----
#pragma unroll
    for (int mf = 0; mf < 4; mf++) {
        int r0 = rowBase + wM * 64 + mf * 16 + g;
        int r1 = r0 + 8;
#pragma unroll
        for (int nf = 0; nf < 4; nf++) {
            int c = wN * 32 + nf * 8 + 2 * t;
            if (r0 < M) *(__half2*)&g_fth[r0 * FDIM + c] =
                __floats2half2_rn(acc[mf][nf][0], acc[mf][nf][1]);
            if (r1 < M) *(__half2*)&g_fth[r1 * FDIM + c] =
                __floats2half2_rn(acc[mf][nf][2], acc[mf][nf][3]);
        }
    }
}

// ---------------------------------------------------------------------------
// vec: vl[k] = sum_d fc_w[k][d]*attn_l[d] (d<32), vr likewise. 1 block x 128.
// ---------------------------------------------------------------------------
__global__ void vec_kernel(const float* __restrict__ fc_w,
                           const float* __restrict__ attn_l,
                           const float* __restrict__ attn_r)
{
    __shared__ float al[32], ar[32];
    int k = threadIdx.x;
    if (k < 32) { al[k] = attn_l[k]; ar[k] = attn_r[k]; }
    __syncthreads();
    float sl = 0.f, sr = 0.f;
#pragma unroll
    for (int d = 0; d < 32; d++) {
        float w = fc_w[k * 128 + d];
        sl = fmaf(w, al[d], sl);
        sr = fmaf(w, ar[d], sr);
    }
    g_vl[k] = sl;
    g_vr[k] = sr;
}

// ---------------------------------------------------------------------------
// scores: sl[n] = inputs[n]·vl, sr[n] = inputs[n]·vr. Warp per node.
// ---------------------------------------------------------------------------
__global__ void __launch_bounds__(256) score_kernel(
    const float* __restrict__ inputs, int N)
{
    int gw = (blockIdx.x * blockDim.x + threadIdx.x) >> 5;
    int lane = threadIdx.x & 31;
    if (gw >= N) return;
    float4 x  = *(const float4*)&inputs[gw * 128 + lane * 4];
    float4 vl = *(const float4*)&g_vl[lane * 4];
    float4 vr = *(const float4*)&g_vr[lane * 4];
    float pl = x.x * vl.x + x.y * vl.y + x.z * vl.z + x.w * vl.w;
    float pr = x.x * vr.x + x.y * vr.y + x.z * vr.z + x.w * vr.w;
#pragma unroll
    for (int off = 16; off > 0; off >>= 1) {
        pl += __shfl_xor_sync(0xFFFFFFFFu, pl, off);
        pr += __shfl_xor_sync(0xFFFFFFFFu, pr, off);
    }
    if (lane == 0) { g_sl[gw] = pl; g_sr[gw] = pr; }
}

// ---------------------------------------------------------------------------
// degree histogram (8 edges per thread)
// ---------------------------------------------------------------------------
__global__ void hist_kernel(const int* __restrict__ dst, int E) {
    int base = (blockIdx.x * blockDim.x + threadIdx.x) * 8;
    if (base + 7 < E) {
        int4 d0 = *(const int4*)&dst[base];
        int4 d1 = *(const int4*)&dst[base + 4];
        atomicAdd(&g_deg[d0.x], 1);
        atomicAdd(&g_deg[d0.y], 1);
        atomicAdd(&g_deg[d0.z], 1);
        atomicAdd(&g_deg[d0.w], 1);
        atomicAdd(&g_deg[d1.x], 1);
        atomicAdd(&g_deg[d1.y], 1);
        atomicAdd(&g_deg[d1.z], 1);
        atomicAdd(&g_deg[d1.w], 1);
    } else {
        for (int e = base; e < E; e++) atomicAdd(&g_deg[dst[e]], 1);
    }
}

// ---------------------------------------------------------------------------
// scan1: per-block (1024) exclusive scan of g_deg; block totals -> g_bsum
// ---------------------------------------------------------------------------
__global__ void __launch_bounds__(256) scan1_kernel(int N) {
    __shared__ int sh[256];
    int t = threadIdx.x;
    int idx = blockIdx.x * 1024 + t * 4;

    int v0 = (idx + 0 < N) ? g_deg[idx + 0] : 0;
    int v1 = (idx + 1 < N) ? g_deg[idx + 1] : 0;
    int v2 = (idx + 2 < N) ? g_deg[idx + 2] : 0;
    int v3 = (idx + 3 < N) ? g_deg[idx + 3] : 0;
    int s = v0 + v1 + v2 + v3;

    sh[t] = s;
    __syncthreads();
#pragma unroll
    for (int d = 1; d < 256; d <<= 1) {
        int x = (t >= d) ? sh[t - d] : 0;
        __syncthreads();
        sh[t] += x;
        __syncthreads();
    }
    int toff = sh[t] - s;

    if (idx + 0 < N) g_off[idx + 0] = toff;
    if (idx + 1 < N) g_off[idx + 1] = toff + v0;
    if (idx + 2 < N) g_off[idx + 2] = toff + v0 + v1;
    if (idx + 3 < N) g_off[idx + 3] = toff + v0 + v1 + v2;

    if (t == 255) g_bsum[blockIdx.x] = sh[255];
}

// ---------------------------------------------------------------------------
// scan23: per-block base reduction + offset add + cursor init (grid <= 256)
// ---------------------------------------------------------------------------
__global__ void __launch_bounds__(256) scan23_kernel(int N) {
    __shared__ int sh[256];
    int t = threadIdx.x;
    int bid = blockIdx.x;
    sh[t] = (t < bid) ? g_bsum[t] : 0;
    __syncthreads();
#pragma unroll
    for (int s = 128; s > 0; s >>= 1) {
        if (t < s) sh[t] += sh[t + s];
        __syncthreads();
    }
    int base = sh[0];

    int idx = bid * 1024 + t * 4;
#pragma unroll
    for (int k = 0; k < 4; k++) {
        if (idx + k < N) {
            int o = g_off[idx + k] + base;
            g_off[idx + k] = o;
            g_cur[idx + k] = o;
        }
    }
}

// ---------------------------------------------------------------------------
// scatter: 4 edges per thread, packed (src, w), CSR order
// ---------------------------------------------------------------------------
__global__ void __launch_bounds__(256) scatter_kernel(
    const int* __restrict__ src, const int* __restrict__ dst, int E)
{
    int base = (blockIdx.x * blockDim.x + threadIdx.x) * 4;
    if (base + 3 < E) {
        int4 s4 = *(const int4*)&src[base];
        int4 d4 = *(const int4*)&dst[base];
        float x0 = g_sl[s4.x] + g_sr[d4.x];
        float x1 = g_sl[s4.y] + g_sr[d4.y];
        float x2 = g_sl[s4.z] + g_sr[d4.z];
        float x3 = g_sl[s4.w] + g_sr[d4.w];
        x0 = (x0 >= 0.0f) ? x0 : ALPHA * x0;
        x1 = (x1 >= 0.0f) ? x1 : ALPHA * x1;
        x2 = (x2 >= 0.0f) ? x2 : ALPHA * x2;
        x3 = (x3 >= 0.0f) ? x3 : ALPHA * x3;
        float w0 = expf(x0);
        float w1 = expf(x1);
        float w2 = expf(x2);
        float w3 = expf(x3);
        int p0 = atomicAdd(&g_cur[d4.x], 1);
        int p1 = atomicAdd(&g_cur[d4.y], 1);
        int p2 = atomicAdd(&g_cur[d4.z], 1);
        int p3 = atomicAdd(&g_cur[d4.w], 1);
        g_edge[p0] = make_float2(__int_as_float(s4.x), w0);
        g_edge[p1] = make_float2(__int_as_float(s4.y), w1);
        g_edge[p2] = make_float2(__int_as_float(s4.z), w2);
        g_edge[p3] = make_float2(__int_as_float(s4.w), w3);
    } else {
        for (int e = base; e < E; e++) {
            int s = src[e];
            int d = dst[e];
            float x = g_sl[s] + g_sr[d];
            x = (x >= 0.0f) ? x : ALPHA * x;
            float w = expf(x);
            int pos = atomicAdd(&g_cur[d], 1);
            g_edge[pos] = make_float2(__int_as_float(s), w);
        }
    }
}

// ---------------------------------------------------------------------------
// aggregate: warp per dst node, fp16 gather, unroll-8 for MLP, fused normalize
// ---------------------------------------------------------------------------
__device__ __forceinline__ void acc_edge(
    float2 r, int lane, float4& acc, float& wsum)
{
    int   s = __float_as_int(r.x);
    float w = r.y;
    uint2 raw = *(const uint2*)&g_fth[s * FDIM + lane * 4];
    float2 f0 = __half22float2(*reinterpret_cast<__half2*>(&raw.x));
    float2 f1 = __half22float2(*reinterpret_cast<__half2*>(&raw.y));
    wsum += w;
    acc.x = fmaf(w, f0.x, acc.x);
    acc.y = fmaf(w, f0.y, acc.y);
    acc.z = fmaf(w, f1.x, acc.z);
    acc.w = fmaf(w, f1.y, acc.w);
}

__global__ void __launch_bounds__(256) aggregate_kernel(
    float* __restrict__ out, int N)
{
    int d = (blockIdx.x * blockDim.x + threadIdx.x) >> 5;
    int lane = threadIdx.x & 31;
    if (d >= N) return;

    int i   = g_off[d];
    int end = g_cur[d];

    float4 acc = make_float4(0.0f, 0.0f, 0.0f, 0.0f);
    float wsum = 0.0f;

    for (; i + 8 <= end; i += 8) {
        float2 r[8];
#pragma unroll
        for (int j = 0; j < 8; j++) r[j] = g_edge[i + j];
        uint2 a[8];
#pragma unroll
        for (int j = 0; j < 8; j++) {
            int s = __float_as_int(r[j].x);
            a[j] = *(const uint2*)&g_fth[s * FDIM + lane * 4];
        }
#pragma unroll
        for (int j = 0; j < 8; j++) {
            float w = r[j].y;
            float2 f0 = __half22float2(*reinterpret_cast<__half2*>(&a[j].x));
            float2 f1 = __half22float2(*reinterpret_cast<__half2*>(&a[j].y));
            acc.x = fmaf(w, f0.x, acc.x);
            acc.y = fmaf(w, f0.y, acc.y);
            acc.z = fmaf(w, f1.x, acc.z);
            acc.w = fmaf(w, f1.y, acc.w);
            wsum += w;
        }
    }
    for (; i < end; i++) {
        acc_edge(g_edge[i], lane, acc, wsum);
    }

    float inv = (wsum > 0.0f) ? (1.0f / wsum) : 0.0f;
    float4 o = make_float4(acc.x * inv, acc.y * inv, acc.z * inv, acc.w * inv);
    *(float4*)&out[d * FDIM + lane * 4] = o;
}

// ---------------------------------------------------------------------------
extern "C" void kernel_launch(void* const* d_in, const int* in_sizes, int n_in,
                              void* d_out, int out_size)
{
    const float* inputs = (const float*)d_in[0];   // (N,128)
    const int*   src    = (const int*)d_in[1];     // (E,)
    const int*   dst    = (const int*)d_in[2];     // (E,)
    const float* fc_w   = (const float*)d_in[3];   // (128,128)
    const float* attn_l = (const float*)d_in[4];   // (32,)
    const float* attn_r = (const float*)d_in[5];   // (32,)
    float* out = (float*)d_out;                    // (N,128)

    int N = in_sizes[0] / FDIM;
    int E = in_sizes[1];
    int nb = (N + 1023) / 1024;                    // <= 256 required by scan23

    // one-time host-side setup (no device memory; capture-safe)
    static cudaStream_t s2 = nullptr, s3 = nullptr;
    static cudaEvent_t ev_fork = nullptr, ev_score = nullptr, ev_edge = nullptr;
    if (s2 == nullptr) {
        cudaStreamCreateWithFlags(&s2, cudaStreamNonBlocking);
        cudaStreamCreateWithFlags(&s3, cudaStreamNonBlocking);
        cudaEventCreateWithFlags(&ev_fork, cudaEventDisableTiming);
        cudaEventCreateWithFlags(&ev_score, cudaEventDisableTiming);
        cudaEventCreateWithFlags(&ev_edge, cudaEventDisableTiming);
        cudaFuncSetAttribute(gemm_tc_kernel,
                             cudaFuncAttributeMaxDynamicSharedMemorySize,
                             GEMM_SMEM_WORDS * 4);
    }

    int* deg_ptr;
    cudaGetSymbolAddress((void**)&deg_ptr, g_deg);

    // ---- fork ----
    cudaEventRecord(ev_fork, 0);
    cudaStreamWaitEvent(s2, ev_fork, 0);
    cudaStreamWaitEvent(s3, ev_fork, 0);

    // s3: scores via precomputed projection vectors (exact fp32 reassociation)
    vec_kernel<<<1, 128, 0, s3>>>(fc_w, attn_l, attn_r);
    score_kernel<<<(N * 32 + 255) / 256, 256, 0, s3>>>(inputs, N);
    cudaEventRecord(ev_score, s3);

    // s2: CSR build, then scatter (after scores) — all concurrent with GEMM
    cudaMemsetAsync(deg_ptr, 0, (size_t)N * sizeof(int), s2);
    hist_kernel<<<(E / 8 + 255) / 256, 256, 0, s2>>>(dst, E);
    scan1_kernel<<<nb, 256, 0, s2>>>(N);
    scan23_kernel<<<nb, 256, 0, s2>>>(N);
    cudaStreamWaitEvent(s2, ev_score, 0);
    scatter_kernel<<<(E / 4 + 255) / 256, 256, 0, s2>>>(src, dst, E);
    cudaEventRecord(ev_edge, s2);

    // main: GEMM -> g_fth (scalar-LDS bf16x3; fastest measured)
    gemm_tc_kernel<<<(N + 127) / 128, 256, GEMM_SMEM_WORDS * 4>>>(
        inputs, fc_w, N);

    // join: aggregate needs g_fth (main) + edge records (s2)
    cudaStreamWaitEvent(0, ev_edge, 0);
    {
        long long threads = (long long)N * 32;
        aggregate_kernel<<<(int)((threads + 255) / 256), 256>>>(out, N);
    }
}

// round 16
// speedup vs baseline: 1.1272x; 1.1272x over previous
#include <cuda_runtime.h>
#include <cuda_fp16.h>
#include <cuda_bf16.h>
#include <stdint.h>

// Problem constants: N=100000, E=1600000, IN_DIM=128, H*D=128, head0 D=32
#define NNODES   100000
#define EMAX     1600000
#define FDIM     128
#define ALPHA    0.2f

// -------- scratch (allocation-free rule: __device__ globals) ---------------
__device__ __half  g_fth[NNODES * FDIM]; // fc output in fp16 (gather payload)
__device__ float   g_sl[NNODES];         // head-0 left scores (fp32)
__device__ float   g_sr[NNODES];         // head-0 right scores
__device__ int     g_deg[NNODES];
__device__ int     g_off[NNODES];
__device__ int     g_cur[NNODES];
__device__ int     g_csr[EMAX];          // src ids permuted into CSR-by-dst order
__device__ int     g_bsum[512];

// ---------------------------------------------------------------------------
// GEMM: bf16x3 (hi/lo split, 3 MMAs: hh + lh + hl) m16n8k16, scalar smem
// fragment loads (fastest measured config), fused score epilogue.
// Full B resident in smem. BM=128, 8 warps, warp tile 64x32.
// ---------------------------------------------------------------------------
#define ASW 20   // A chunk stride in words; frag loads bank (4g+t), conflict-free
#define BSW 68   // B stride in words; frag loads bank-clean
#define GEMM_SMEM_WORDS (2*128*BSW + 2*128*ASW)   // 22528 words = 90112 B

__device__ __forceinline__ void cvt_hilo(float x, float y, unsigned& h, unsigned& l) {
    __nv_bfloat162 hb = __floats2bfloat162_rn(x, y);
    float2 hf = __bfloat1622float2(hb);
    __nv_bfloat162 lb = __floats2bfloat162_rn(x - hf.x, y - hf.y);
    h = *reinterpret_cast<unsigned*>(&hb);
    l = *reinterpret_cast<unsigned*>(&lb);
}

__device__ __forceinline__ void mma_bf16(
    float& c0, float& c1, float& c2, float& c3,
    unsigned a0, unsigned a1, unsigned a2, unsigned a3,
    unsigned b0, unsigned b1)
{
    asm volatile(
        "mma.sync.aligned.m16n8k16.row.col.f32.bf16.bf16.f32 "
        "{%0,%1,%2,%3}, {%4,%5,%6,%7}, {%8,%9}, {%0,%1,%2,%3};"
        : "+f"(c0), "+f"(c1), "+f"(c2), "+f"(c3)
        : "r"(a0), "r"(a1), "r"(a2), "r"(a3), "r"(b0), "r"(b1));
}

__global__ void __launch_bounds__(256, 2) gemm_tc_kernel(
    const float* __restrict__ A, const float* __restrict__ B,
    const float* __restrict__ attn_l, const float* __restrict__ attn_r, int M)
{
    extern __shared__ unsigned sm[];
    unsigned* sBhi = sm;                       // 128*BSW
    unsigned* sBlo = sm + 128 * BSW;
    unsigned* sAhi = sm + 2 * 128 * BSW;       // 128*ASW
    unsigned* sAlo = sm + 2 * 128 * BSW + 128 * ASW;

    int tid  = threadIdx.x;
    int wid  = tid >> 5;
    int lane = tid & 31;
    int g    = lane >> 2;   // groupID 0..7
    int t    = lane & 3;    // thread-in-group 0..3
    int wM   = wid >> 2;    // 0..1  (64 rows each)
    int wN   = wid & 3;     // 0..3  (32 cols each)
    int rowBase = blockIdx.x * 128;

    // ---- load FULL B (128x128) once: hi/lo bf16, [n][k-pairs] ----
#pragma unroll
    for (int i = 0; i < 32; i++) {
        int w = i * 256 + tid;
        int n = w & 127;
        int kp = w >> 7;
        float f0 = B[(2 * kp) * 128 + n];
        float f1 = B[(2 * kp + 1) * 128 + n];
        unsigned h, l;
        cvt_hilo(f0, f1, h, l);
        sBhi[n * BSW + kp] = h;
        sBlo[n * BSW + kp] = l;
    }

    float acc[4][4][4];
#pragma unroll
    for (int i = 0; i < 4; i++)
#pragma unroll
        for (int j = 0; j < 4; j++)
#pragma unroll
            for (int k = 0; k < 4; k++) acc[i][j][k] = 0.0f;

    for (int kk = 0; kk < 128; kk += 32) {
        // ---- load A chunk 128x32 (1024 f4: 4 per thread), hi/lo bf16 ----
#pragma unroll
        for (int i = 0; i < 4; i++) {
            int idx = i * 256 + tid;
            int r  = idx >> 3;        // row 0..127
            int c4 = idx & 7;         // f4-col 0..7
            int gr = rowBase + r;
            float4 v = make_float4(0.f, 0.f, 0.f, 0.f);
            if (gr < M) v = *(const float4*)&A[gr * 128 + kk + c4 * 4];
            unsigned h0, l0, h1, l1;
            cvt_hilo(v.x, v.y, h0, l0);
            cvt_hilo(v.z, v.w, h1, l1);
            int o = r * ASW + c4 * 2;
            sAhi[o] = h0; sAhi[o + 1] = h1;
            sAlo[o] = l0; sAlo[o + 1] = l1;
        }
        __syncthreads();

#pragma unroll
        for (int ks = 0; ks < 2; ks++) {
            int kw  = ks * 8;          // word offset within A chunk
            int bkw = kk / 2 + ks * 8; // word offset within B rows

            unsigned bh[4][2], bl[4][2];
#pragma unroll
            for (int nf = 0; nf < 4; nf++) {
                int bn = wN * 32 + nf * 8 + g;
                bh[nf][0] = sBhi[bn * BSW + bkw + t];
                bh[nf][1] = sBhi[bn * BSW + bkw + t + 4];
                bl[nf][0] = sBlo[bn * BSW + bkw + t];
                bl[nf][1] = sBlo[bn * BSW + bkw + t + 4];
            }
#pragma unroll
            for (int mf = 0; mf < 4; mf++) {
                int ar = wM * 64 + mf * 16 + g;
                unsigned ah0 = sAhi[ar * ASW + kw + t];
                unsigned ah1 = sAhi[(ar + 8) * ASW + kw + t];
                unsigned ah2 = sAhi[ar * ASW + kw + t + 4];
                unsigned ah3 = sAhi[(ar + 8) * ASW + kw + t + 4];
                unsigned al0 = sAlo[ar * ASW + kw + t];
                unsigned al1 = sAlo[(ar + 8) * ASW + kw + t];
                unsigned al2 = sAlo[ar * ASW + kw + t + 4];
                unsigned al3 = sAlo[(ar + 8) * ASW + kw + t + 4];
#pragma unroll
                for (int nf = 0; nf < 4; nf++) {
                    mma_bf16(acc[mf][nf][0], acc[mf][nf][1], acc[mf][nf][2], acc[mf][nf][3],
                             ah0, ah1, ah2, ah3, bh[nf][0], bh[nf][1]);
                    mma_bf16(acc[mf][nf][0], acc[mf][nf][1], acc[mf][nf][2], acc[mf][nf][3],
                             al0, al1, al2, al3, bh[nf][0], bh[nf][1]);
                    mma_bf16(acc[mf][nf][0], acc[mf][nf][1], acc[mf][nf][2], acc[mf][nf][3],
                             ah0, ah1, ah2, ah3, bl[nf][0], bl[nf][1]);
                }
            }
        }
        __syncthreads();
    }

    // ---- epilogue: fp16 store + fused head-0 scores (wN==0 warps own cols 0..31)
#pragma unroll
    for (int mf = 0; mf < 4; mf++) {
        int r0 = rowBase + wM * 64 + mf * 16 + g;
        int r1 = r0 + 8;
        float pl0 = 0.f, pl1 = 0.f, pr0 = 0.f, pr1 = 0.f;
#pragma unroll
        for (int nf = 0; nf < 4; nf++) {
            int c = wN * 32 + nf * 8 + 2 * t;
            float c0 = acc[mf][nf][0], c1 = acc[mf][nf][1];
            float c2 = acc[mf][nf][2], c3 = acc[mf][nf][3];
            if (r0 < M) *(__half2*)&g_fth[r0 * FDIM + c] = __floats2half2_rn(c0, c1);
            if (r1 < M) *(__half2*)&g_fth[r1 * FDIM + c] = __floats2half2_rn(c2, c3);
            if (wN == 0) {
                float al0 = attn_l[c], al1 = attn_l[c + 1];
                float ar0 = attn_r[c], ar1 = attn_r[c + 1];
                pl0 = fmaf(c0, al0, fmaf(c1, al1, pl0));
                pl1 = fmaf(c2, al0, fmaf(c3, al1, pl1));
                pr0 = fmaf(c0, ar0, fmaf(c1, ar1, pr0));
                pr1 = fmaf(c2, ar0, fmaf(c3, ar1, pr1));
            }
        }
        if (wN == 0) {
#pragma unroll
            for (int off = 1; off < 4; off <<= 1) {
                pl0 += __shfl_xor_sync(0xFFFFFFFFu, pl0, off);
                pl1 += __shfl_xor_sync(0xFFFFFFFFu, pl1, off);
                pr0 += __shfl_xor_sync(0xFFFFFFFFu, pr0, off);
                pr1 += __shfl_xor_sync(0xFFFFFFFFu, pr1, off);
            }
            if (t == 0) {
                if (r0 < M) { g_sl[r0] = pl0; g_sr[r0] = pr0; }
                if (r1 < M) { g_sl[r1] = pl1; g_sr[r1] = pr1; }
            }
        }
    }
}

// ---------------------------------------------------------------------------
// degree histogram (8 edges per thread)
// ---------------------------------------------------------------------------
__global__ void hist_kernel(const int* __restrict__ dst, int E) {
    int base = (blockIdx.x * blockDim.x + threadIdx.x) * 8;
    if (base + 7 < E) {
        int4 d0 = *(const int4*)&dst[base];
        int4 d1 = *(const int4*)&dst[base + 4];
        atomicAdd(&g_deg[d0.x], 1);
        atomicAdd(&g_deg[d0.y], 1);
        atomicAdd(&g_deg[d0.z], 1);
        atomicAdd(&g_deg[d0.w], 1);
        atomicAdd(&g_deg[d1.x], 1);
        atomicAdd(&g_deg[d1.y], 1);
        atomicAdd(&g_deg[d1.z], 1);
        atomicAdd(&g_deg[d1.w], 1);
    } else {
        for (int e = base; e < E; e++) atomicAdd(&g_deg[dst[e]], 1);
    }
}

// ---------------------------------------------------------------------------
// scan1: per-block (1024) exclusive scan of g_deg; block totals -> g_bsum
// ---------------------------------------------------------------------------
__global__ void __launch_bounds__(256) scan1_kernel(int N) {
    __shared__ int sh[256];
    int t = threadIdx.x;
    int idx = blockIdx.x * 1024 + t * 4;

    int v0 = (idx + 0 < N) ? g_deg[idx + 0] : 0;
    int v1 = (idx + 1 < N) ? g_deg[idx + 1] : 0;
    int v2 = (idx + 2 < N) ? g_deg[idx + 2] : 0;
    int v3 = (idx + 3 < N) ? g_deg[idx + 3] : 0;
    int s = v0 + v1 + v2 + v3;

    sh[t] = s;
    __syncthreads();
#pragma unroll
    for (int d = 1; d < 256; d <<= 1) {
        int x = (t >= d) ? sh[t - d] : 0;
        __syncthreads();
        sh[t] += x;
        __syncthreads();
    }
    int toff = sh[t] - s;

    if (idx + 0 < N) g_off[idx + 0] = toff;
    if (idx + 1 < N) g_off[idx + 1] = toff + v0;
    if (idx + 2 < N) g_off[idx + 2] = toff + v0 + v1;
    if (idx + 3 < N) g_off[idx + 3] = toff + v0 + v1 + v2;

    if (t == 255) g_bsum[blockIdx.x] = sh[255];
}

// ---------------------------------------------------------------------------
// scan23: per-block base reduction + offset add + cursor init (grid <= 256)
// ---------------------------------------------------------------------------
__global__ void __launch_bounds__(256) scan23_kernel(int N) {
    __shared__ int sh[256];
    int t = threadIdx.x;
    int bid = blockIdx.x;
    sh[t] = (t < bid) ? g_bsum[t] : 0;
    __syncthreads();
#pragma unroll
    for (int s = 128; s > 0; s >>= 1) {
        if (t < s) sh[t] += sh[t + s];
        __syncthreads();
    }
    int base = sh[0];

    int idx = bid * 1024 + t * 4;
#pragma unroll
    for (int k = 0; k < 4; k++) {
        if (idx + k < N) {
            int o = g_off[idx + k] + base;
            g_off[idx + k] = o;
            g_cur[idx + k] = o;
        }
    }
}

// ---------------------------------------------------------------------------
// perm: CSR-by-dst permutation of src ids (no scores needed -> hides under GEMM)
// ---------------------------------------------------------------------------
__global__ void __launch_bounds__(256) perm_kernel(
    const int* __restrict__ src, const int* __restrict__ dst, int E)
{
    int base = (blockIdx.x * blockDim.x + threadIdx.x) * 4;
    if (base + 3 < E) {
        int4 s4 = *(const int4*)&src[base];
        int4 d4 = *(const int4*)&dst[base];
        int p0 = atomicAdd(&g_cur[d4.x], 1);
        int p1 = atomicAdd(&g_cur[d4.y], 1);
        int p2 = atomicAdd(&g_cur[d4.z], 1);
        int p3 = atomicAdd(&g_cur[d4.w], 1);
        g_csr[p0] = s4.x;
        g_csr[p1] = s4.y;
        g_csr[p2] = s4.z;
        g_csr[p3] = s4.w;
    } else {
        for (int e = base; e < E; e++) {
            int pos = atomicAdd(&g_cur[dst[e]], 1);
            g_csr[pos] = src[e];
        }
    }
}

// ---------------------------------------------------------------------------
// aggregate: warp per dst node. Weight phase (one exp per edge, staged in
// smem) + MLP-8 fp16 gather + fused normalize. No separate scatter pass.
// ---------------------------------------------------------------------------
__global__ void __launch_bounds__(256) aggregate_kernel(
    float* __restrict__ out, int N)
{
    __shared__ float swv[8][32];
    __shared__ int   ssv[8][32];

    int warp = threadIdx.x >> 5;
    int d = (blockIdx.x * blockDim.x + threadIdx.x) >> 5;
    int lane = threadIdx.x & 31;
    if (d >= N) return;

    int i   = g_off[d];
    int end = g_cur[d];
    float sr_d = g_sr[d];

    float4 acc = make_float4(0.0f, 0.0f, 0.0f, 0.0f);
    float wsum = 0.0f;

    while (i < end) {
        int cnt = min(32, end - i);

        // ---- weight phase: lane j computes edge i+j's (src, w) ----
        int   s_j = 0;
        float w_j = 0.0f;
        if (lane < cnt) {
            s_j = g_csr[i + lane];                 // coalesced
            float x = g_sl[s_j] + sr_d;            // random 4B gather (L2)
            x = (x >= 0.0f) ? x : ALPHA * x;
            w_j = expf(x);
        }
        ssv[warp][lane] = s_j;
        swv[warp][lane] = w_j;
        __syncwarp();

        // ---- gather phase: MLP-8 over staged records ----
        int k = 0;
        for (; k + 8 <= cnt; k += 8) {
            int   s[8];
            float w[8];
#pragma unroll
            for (int j = 0; j < 8; j++) { s[j] = ssv[warp][k + j]; w[j] = swv[warp][k + j]; }
            uint2 a[8];
#pragma unroll
            for (int j = 0; j < 8; j++)
                a[j] = *(const uint2*)&g_fth[s[j] * FDIM + lane * 4];
#pragma unroll
            for (int j = 0; j < 8; j++) {
                float2 f0 = __half22float2(*reinterpret_cast<__half2*>(&a[j].x));
                float2 f1 = __half22float2(*reinterpret_cast<__half2*>(&a[j].y));
                acc.x = fmaf(w[j], f0.x, acc.x);
                acc.y = fmaf(w[j], f0.y, acc.y);
                acc.z = fmaf(w[j], f1.x, acc.z);
                acc.w = fmaf(w[j], f1.y, acc.w);
                wsum += w[j];
            }
        }
        for (; k < cnt; k++) {
            int   s = ssv[warp][k];
            float w = swv[warp][k];
            uint2 a = *(const uint2*)&g_fth[s * FDIM + lane * 4];
            float2 f0 = __half22float2(*reinterpret_cast<__half2*>(&a.x));
            float2 f1 = __half22float2(*reinterpret_cast<__half2*>(&a.y));
            acc.x = fmaf(w, f0.x, acc.x);
            acc.y = fmaf(w, f0.y, acc.y);
            acc.z = fmaf(w, f1.x, acc.z);
            acc.w = fmaf(w, f1.y, acc.w);
            wsum += w;
        }
        __syncwarp();
        i += cnt;
    }

    float inv = (wsum > 0.0f) ? (1.0f / wsum) : 0.0f;
    float4 o = make_float4(acc.x * inv, acc.y * inv, acc.z * inv, acc.w * inv);
    *(float4*)&out[d * FDIM + lane * 4] = o;
}

// ---------------------------------------------------------------------------
extern "C" void kernel_launch(void* const* d_in, const int* in_sizes, int n_in,
                              void* d_out, int out_size)
{
    const float* inputs = (const float*)d_in[0];   // (N,128)
    const int*   src    = (const int*)d_in[1];     // (E,)
    const int*   dst    = (const int*)d_in[2];     // (E,)
    const float* fc_w   = (const float*)d_in[3];   // (128,128)
    const float* attn_l = (const float*)d_in[4];   // (32,)
    const float* attn_r = (const float*)d_in[5];   // (32,)
    float* out = (float*)d_out;                    // (N,128)

    int N = in_sizes[0] / FDIM;
    int E = in_sizes[1];
    int nb = (N + 1023) / 1024;                    // <= 256 required by scan23

    // one-time host-side setup (no device memory; capture-safe)
    static cudaStream_t s2 = nullptr;
    static cudaEvent_t ev_fork = nullptr, ev_join = nullptr;
    if (s2 == nullptr) {
        cudaStreamCreateWithFlags(&s2, cudaStreamNonBlocking);
        cudaEventCreateWithFlags(&ev_fork, cudaEventDisableTiming);
        cudaEventCreateWithFlags(&ev_join, cudaEventDisableTiming);
        cudaFuncSetAttribute(gemm_tc_kernel,
                             cudaFuncAttributeMaxDynamicSharedMemorySize,
                             GEMM_SMEM_WORDS * 4);
    }

    int* deg_ptr;
    cudaGetSymbolAddress((void**)&deg_ptr, g_deg);

    // ---- fork: CSR build + permutation (src/dst only) hides under GEMM ----
    cudaEventRecord(ev_fork, 0);
    cudaStreamWaitEvent(s2, ev_fork, 0);

    cudaMemsetAsync(deg_ptr, 0, (size_t)N * sizeof(int), s2);
    hist_kernel<<<(E / 8 + 255) / 256, 256, 0, s2>>>(dst, E);
    scan1_kernel<<<nb, 256, 0, s2>>>(N);
    scan23_kernel<<<nb, 256, 0, s2>>>(N);
    perm_kernel<<<(E / 4 + 255) / 256, 256, 0, s2>>>(src, dst, E);
    cudaEventRecord(ev_join, s2);

    // ---- main: GEMM + fused scores (bf16x3, scalar frag loads) ----
    gemm_tc_kernel<<<(N + 127) / 128, 256, GEMM_SMEM_WORDS * 4>>>(
        inputs, fc_w, attn_l, attn_r, N);

    // ---- join: aggregate needs g_fth+scores (main) + permutation (s2) ----
    cudaStreamWaitEvent(0, ev_join, 0);
    {
        long long threads = (long long)N * 32;
        aggregate_kernel<<<(int)((threads + 255) / 256), 256>>>(out, N);
    }
}